// round 15
// baseline (speedup 1.0000x reference)
#include <cuda_runtime.h>
#include <cuda_fp16.h>
#include <math.h>
#include <stdint.h>

#define BB 2048
#define DD 2048
#define MAXN (1.0f - 1e-5f)
#define MINN 1e-10f

// ---------------- scratch ----------------
__device__ float g_xn[BB];
__device__ float g_hn[BB];
__device__ float g_hsc[BB];
__device__ float g_rphn[BB];
__device__ __half g_G0[BB * DD];
__device__ __half g_G1[BB * DD];
__device__ __half g_G2[BB * DD];
__device__ __half g_G3[BB * DD];
__device__ __half g_G4[BB * DD];
__device__ float g_z[BB * DD];
__device__ __half g_xhi[BB * DD];
__device__ __half g_hhi[BB * DD];
__device__ __half g_phi[BB * DD];
__device__ __half g_whi[5 * DD * DD];

// =================== helpers ===================
__device__ __forceinline__ uint32_t smem_u32(const void* p) {
    uint32_t a;
    asm("{ .reg .u64 t; cvta.to.shared.u64 t, %1; cvt.u32.u64 %0, t; }" : "=r"(a) : "l"(p));
    return a;
}

__device__ __forceinline__ void hi4h(float4 v, uint2& h) {
    __half2 h0 = __floats2half2_rn(v.x, v.y);
    __half2 h1 = __floats2half2_rn(v.z, v.w);
    h.x = *reinterpret_cast<uint32_t*>(&h0);
    h.y = *reinterpret_cast<uint32_t*>(&h1);
}

__device__ __forceinline__ float4 h4f(uint2 u) {
    __half2 a = *reinterpret_cast<__half2*>(&u.x);
    __half2 b = *reinterpret_cast<__half2*>(&u.y);
    float2 fa = __half22float2(a), fb = __half22float2(b);
    return make_float4(fa.x, fa.y, fb.x, fb.y);
}

#define STS128U4(addr, v) \
    asm volatile("st.shared.v4.b32 [%0], {%1,%2,%3,%4};" \
                 :: "r"(addr), "r"((v).x), "r"((v).y), "r"((v).z), "r"((v).w) : "memory")

__device__ __forceinline__ void ldmatrix_x4(uint32_t* r, uint32_t addr) {
    asm volatile("ldmatrix.sync.aligned.m8n8.x4.shared.b16 {%0,%1,%2,%3}, [%4];"
                 : "=r"(r[0]), "=r"(r[1]), "=r"(r[2]), "=r"(r[3]) : "r"(addr));
}
__device__ __forceinline__ void ldmatrix_x4_t(uint32_t* r, uint32_t addr) {
    asm volatile("ldmatrix.sync.aligned.m8n8.x4.trans.shared.b16 {%0,%1,%2,%3}, [%4];"
                 : "=r"(r[0]), "=r"(r[1]), "=r"(r[2]), "=r"(r[3]) : "r"(addr));
}
__device__ __forceinline__ void mma16816(float* d, const uint32_t* a, uint32_t b0, uint32_t b1) {
    asm volatile(
        "mma.sync.aligned.m16n8k16.row.col.f32.f16.f16.f32 "
        "{%0,%1,%2,%3}, {%4,%5,%6,%7}, {%8,%9}, {%0,%1,%2,%3};"
        : "+f"(d[0]), "+f"(d[1]), "+f"(d[2]), "+f"(d[3])
        : "r"(a[0]), "r"(a[1]), "r"(a[2]), "r"(a[3]), "r"(b0), "r"(b1));
}

#define KC 64
#define NCH (DD / KC)
#define A_PITCH 144
#define B_PITCH 272

// =================== fp16 1-term GEMM (2 CTAs/SM, fp16 output) ===================
struct GateArgs {
    const __half* Ahi[4];
    const __half* Bhi[4];
    __half* C[4];
};
#define G_OF_B 18432u
#define G_STG 35840u
#define G_SMEM (2 * 35840)

__global__ void __launch_bounds__(256, 2) mma_gate_kernel(GateArgs ga) {
    extern __shared__ char smem[];
    const __half* __restrict__ Ahi = ga.Ahi[blockIdx.z];
    const __half* __restrict__ Bhi = ga.Bhi[blockIdx.z];
    __half* __restrict__ C = ga.C[blockIdx.z];
    const int m0 = blockIdx.y * 128, n0 = blockIdx.x * 128;
    const uint32_t sbase = smem_u32(smem);
    const int tid = threadIdx.x, wid = tid >> 5, lane = tid & 31;
    const int wm = wid >> 2, wn = wid & 3;

    float acc[4][4][4];
#pragma unroll
    for (int i = 0; i < 4; i++)
#pragma unroll
        for (int j = 0; j < 4; j++)
#pragma unroll
            for (int e = 0; e < 4; e++) acc[i][j][e] = 0.f;

    uint4 sa[4], sbv[4];

#pragma unroll
    for (int u = 0; u < 4; u++) {
        int unit = u * 256 + tid;
        int row = unit >> 3, col = unit & 7;
        sa[u] = *(const uint4*)(Ahi + (size_t)(m0 + row) * DD + col * 8);
        int brow = unit >> 4, bcol = unit & 15;
        sbv[u] = *(const uint4*)(Bhi + (size_t)brow * DD + n0 + bcol * 8);
    }
#pragma unroll
    for (int u = 0; u < 4; u++) {
        int unit = u * 256 + tid;
        int row = unit >> 3, col = unit & 7;
        STS128U4(sbase + (uint32_t)(row * A_PITCH + col * 16), sa[u]);
        int brow = unit >> 4, bcol = unit & 15;
        STS128U4(sbase + G_OF_B + (uint32_t)(brow * B_PITCH + bcol * 16), sbv[u]);
    }

    const int frow = lane & 15;
    const int fcol8 = (lane >> 4) * 8;

    for (int i = 0; i < NCH; i++) {
        const bool has_next = (i + 1) < NCH;
        if (has_next) {
            int kc = (i + 1) * KC;
#pragma unroll
            for (int u = 0; u < 4; u++) {
                int unit = u * 256 + tid;
                int row = unit >> 3, col = unit & 7;
                sa[u] = *(const uint4*)(Ahi + (size_t)(m0 + row) * DD + kc + col * 8);
                int brow = unit >> 4, bcol = unit & 15;
                sbv[u] = *(const uint4*)(Bhi + (size_t)(kc + brow) * DD + n0 + bcol * 8);
            }
        }
        __syncthreads();

        const uint32_t sb = sbase + (uint32_t)(i & 1) * G_STG;
#pragma unroll
        for (int ks = 0; ks < 4; ks++) {
            uint32_t a_h[4][4], b_h[2][4];
            uint32_t acol = (uint32_t)(ks * 16 + fcol8) * 2;
#pragma unroll
            for (int mt = 0; mt < 4; mt++)
                ldmatrix_x4(a_h[mt], sb + (uint32_t)((wm * 64 + mt * 16 + frow) * A_PITCH) + acol);
            uint32_t brow = (uint32_t)((ks * 16 + frow) * B_PITCH);
#pragma unroll
            for (int nh = 0; nh < 2; nh++)
                ldmatrix_x4_t(b_h[nh], sb + G_OF_B + brow + (uint32_t)(wn * 32 + nh * 16 + fcol8) * 2);
#pragma unroll
            for (int mt = 0; mt < 4; mt++)
#pragma unroll
                for (int j = 0; j < 4; j++) {
                    int nh = j >> 1, sbb = (j & 1) * 2;
                    mma16816(acc[mt][j], a_h[mt], b_h[nh][sbb], b_h[nh][sbb + 1]);
                }
        }

        if (has_next) {
            const uint32_t nb = sbase + (uint32_t)((i + 1) & 1) * G_STG;
#pragma unroll
            for (int u = 0; u < 4; u++) {
                int unit = u * 256 + tid;
                int row = unit >> 3, col = unit & 7;
                STS128U4(nb + (uint32_t)(row * A_PITCH + col * 16), sa[u]);
                int brow = unit >> 4, bcol = unit & 15;
                STS128U4(nb + G_OF_B + (uint32_t)(brow * B_PITCH + bcol * 16), sbv[u]);
            }
        }
    }

#pragma unroll
    for (int mt = 0; mt < 4; mt++)
#pragma unroll
        for (int j = 0; j < 4; j++) {
            int row = m0 + wm * 64 + mt * 16 + (lane >> 2);
            int col = n0 + wn * 32 + j * 8 + (lane & 3) * 2;
            __half2 p0 = __floats2half2_rn(acc[mt][j][0], acc[mt][j][1]);
            __half2 p1 = __floats2half2_rn(acc[mt][j][2], acc[mt][j][3]);
            *(__half2*)(C + (size_t)row * DD + col) = p0;
            *(__half2*)(C + (size_t)(row + 8) * DD + col) = p1;
        }
}

// =================== elementwise kernels ===================
template <int NV>
__device__ __forceinline__ void block_reduce(float (&v)[NV]) {
    __shared__ float sm[NV * 8];
    __syncthreads();
    int lane = threadIdx.x & 31, w = threadIdx.x >> 5;
#pragma unroll
    for (int i = 0; i < NV; i++) {
        float x = v[i];
#pragma unroll
        for (int o = 16; o > 0; o >>= 1) x += __shfl_down_sync(0xffffffffu, x, o);
        if (lane == 0) sm[i * 8 + w] = x;
    }
    __syncthreads();
    if (threadIdx.x == 0) {
#pragma unroll
        for (int i = 0; i < NV; i++) {
            float s = 0.f;
#pragma unroll
            for (int j = 0; j < 8; j++) s += sm[i * 8 + j];
            sm[i * 8] = s;
        }
    }
    __syncthreads();
#pragma unroll
    for (int i = 0; i < NV; i++) v[i] = sm[i * 8];
}

__device__ __forceinline__ float artanh_c(float x) { return atanhf(fminf(x, MAXN)); }

__device__ __forceinline__ void proj_coef(float& coef, float& s2) {
    float n = sqrtf(fmaxf(s2, MINN));
    if (n > MAXN) {
        float f = MAXN / n;
        coef *= f;
        s2 *= f * f;
    }
}

__device__ __forceinline__ void transition_coefs(const float* v, float hn, float xn,
                                                 float& fw, float& fu, float& fb, float& f2) {
    float Mw = sqrtf(fmaxf(v[0], MINN));
    float cu = tanhf(Mw / hn * artanh_c(hn)) / Mw;
    float su = cu * cu * v[0];
    proj_coef(cu, su);

    float Mu = sqrtf(fmaxf(v[1], MINN));
    float cv = tanhf(Mu / xn * artanh_c(xn)) / Mu;
    float sv = cv * cv * v[1];
    proj_coef(cv, sv);

    float uv = cu * cv * v[2];
    float a = 1.f + 2.f * uv + sv;
    float c = 1.f - su;
    float den = fmaxf(1.f + 2.f * uv + su * sv, MINN);
    float aw = a * cu / den, au = c * cv / den;
    float q2 = aw * aw * v[0] + 2.f * aw * au * v[2] + au * au * v[1];
    {
        float n = sqrtf(fmaxf(q2, MINN));
        if (n > MAXN) { float f = MAXN / n; aw *= f; au *= f; q2 *= f * f; }
    }

    float qb = aw * v[3] + au * v[4];
    float b2 = v[5];
    float A2 = 1.f + 2.f * qb + b2;
    float C2 = 1.f - q2;
    float den2 = fmaxf(1.f + 2.f * qb + q2 * b2, MINN);
    fw = A2 * aw / den2; fu = A2 * au / den2; fb = C2 / den2;
    f2 = fw * fw * v[0] + fu * fu * v[1] + fb * fb * v[5] +
         2.f * fw * fu * v[2] + 2.f * fw * fb * v[3] + 2.f * fu * fb * v[4];
    {
        float n = sqrtf(fmaxf(f2, MINN));
        if (n > MAXN) { float f = MAXN / n; fw *= f; fu *= f; fb *= f; f2 *= f * f; }
    }
}

// proj inputs: hidden -> hhi (fp16 of h*sc) + hn + hsc ; x -> xhi + xn.  No fp32 hp array.
__global__ void __launch_bounds__(256) proj_norm_kernel(const float* __restrict__ hx,
                                                        const float* __restrict__ hd) {
    int row = blockIdx.x;
    int ish = blockIdx.y;
    const float* src = ish ? hd : hx;
    const float4* p = (const float4*)(src + (size_t)row * DD);
    float4 a = p[threadIdx.x], b = p[threadIdx.x + 256];
    float acc[1] = {a.x * a.x + a.y * a.y + a.z * a.z + a.w * a.w +
                    b.x * b.x + b.y * b.y + b.z * b.z + b.w * b.w};
    block_reduce<1>(acc);
    float n = sqrtf(fmaxf(acc[0], MINN));
    float sc = (n > MAXN) ? (MAXN / n) : 1.f;
    float4 va = make_float4(a.x * sc, a.y * sc, a.z * sc, a.w * sc);
    float4 vb = make_float4(b.x * sc, b.y * sc, b.z * sc, b.w * sc);
    uint2 ha, hb;
    hi4h(va, ha);
    hi4h(vb, hb);
    size_t i0 = (size_t)row * (DD / 4) + threadIdx.x;
    size_t i1 = i0 + 256;
    if (ish) {
        ((uint2*)g_hhi)[i0] = ha; ((uint2*)g_hhi)[i1] = hb;
        if (threadIdx.x == 0) {
            g_hn[row] = fminf(n, MAXN);
            g_hsc[row] = sc;
        }
    } else {
        ((uint2*)g_xhi)[i0] = ha; ((uint2*)g_xhi)[i1] = hb;
        if (threadIdx.x == 0) g_xn[row] = fminf(n, MAXN);
    }
}

struct SplitArgs { const float* src[5]; };
__global__ void __launch_bounds__(256) split_w_kernel(SplitArgs saw) {
    int w = blockIdx.y;
    size_t base = (size_t)blockIdx.x * 512 + threadIdx.x;
#pragma unroll
    for (int it = 0; it < 2; it++) {
        size_t i4 = base + it * 256;
        float4 v = ((const float4*)saw.src[w])[i4];
        size_t o = (size_t)w * (DD * DD / 4) + i4;
        uint2 h;
        hi4h(v, h);
        ((uint2*)g_whi)[o] = h;
    }
}

// fused: z gate -> g_z (fp32), r gate + r_point_h -> phi + rphn.
// hp recomputed as hidden*hsc (R13-identical arithmetic).
__global__ void __launch_bounds__(256) combine_zr_kernel(
    const __half* __restrict__ G0, const __half* __restrict__ G2, const float* __restrict__ bz,
    const __half* __restrict__ G1, const __half* __restrict__ G3, const float* __restrict__ br,
    const float* __restrict__ hidden) {
    int row = blockIdx.x;
    const uint2* wz2 = (const uint2*)(G0 + (size_t)row * DD);
    const uint2* uz2 = (const uint2*)(G2 + (size_t)row * DD);
    const uint2* wr2 = (const uint2*)(G1 + (size_t)row * DD);
    const uint2* ur2 = (const uint2*)(G3 + (size_t)row * DD);
    const float4* bz4 = (const float4*)bz;
    const float4* br4 = (const float4*)br;
    const float4* hd4 = (const float4*)(hidden + (size_t)row * DD);
    const float hsc = g_hsc[row];

    float4 wrv[2], urv[2], hv[2];
    float v[12];
#pragma unroll
    for (int q = 0; q < 12; q++) v[q] = 0.f;
#pragma unroll
    for (int it = 0; it < 2; it++) {
        int j = threadIdx.x + it * 256;
        float4 a = h4f(wz2[j]), b = h4f(uz2[j]), c = h4f(wr2[j]), d = h4f(ur2[j]);
        float4 e = bz4[j], f = br4[j];
        float4 hr = hd4[j];
        wrv[it] = c; urv[it] = d;
        hv[it] = make_float4(hr.x * hsc, hr.y * hsc, hr.z * hsc, hr.w * hsc);
        v[0] += a.x * a.x + a.y * a.y + a.z * a.z + a.w * a.w;
        v[1] += b.x * b.x + b.y * b.y + b.z * b.z + b.w * b.w;
        v[2] += a.x * b.x + a.y * b.y + a.z * b.z + a.w * b.w;
        v[3] += a.x * e.x + a.y * e.y + a.z * e.z + a.w * e.w;
        v[4] += b.x * e.x + b.y * e.y + b.z * e.z + b.w * e.w;
        v[5] += e.x * e.x + e.y * e.y + e.z * e.z + e.w * e.w;
        v[6] += c.x * c.x + c.y * c.y + c.z * c.z + c.w * c.w;
        v[7] += d.x * d.x + d.y * d.y + d.z * d.z + d.w * d.w;
        v[8] += c.x * d.x + c.y * d.y + c.z * d.z + c.w * d.w;
        v[9] += c.x * f.x + c.y * f.y + c.z * f.z + c.w * f.w;
        v[10] += d.x * f.x + d.y * f.y + d.z * f.z + d.w * f.w;
        v[11] += f.x * f.x + f.y * f.y + f.z * f.z + f.w * f.w;
    }
    block_reduce<12>(v);

    float hn = g_hn[row], xn = g_xn[row];

    float fwz, fuz, fbz, f2z;
    transition_coefs(&v[0], hn, xn, fwz, fuz, fbz, f2z);
    float fnz = sqrtf(fmaxf(f2z, MINN));
    float lgz = artanh_c(fnz) / fnz;

    float fwr, fur, fbr, f2r;
    transition_coefs(&v[6], hn, xn, fwr, fur, fbr, f2r);
    float fnr = sqrtf(fmaxf(f2r, MINN));
    float lgr = artanh_c(fnr) / fnr;

    float tv[2][4];
    float s[1] = {0.f};
    float4* oz = (float4*)(g_z + (size_t)row * DD);
#pragma unroll
    for (int it = 0; it < 2; it++) {
        int j = threadIdx.x + it * 256;
        float4 a = h4f(wz2[j]), b = h4f(uz2[j]);
        float4 e = bz4[j];
        float t0 = lgz * (fwz * a.x + fuz * b.x + fbz * e.x);
        float t1 = lgz * (fwz * a.y + fuz * b.y + fbz * e.y);
        float t2 = lgz * (fwz * a.z + fuz * b.z + fbz * e.z);
        float t3 = lgz * (fwz * a.w + fuz * b.w + fbz * e.w);
        oz[j] = make_float4(1.f / (1.f + expf(-t0)), 1.f / (1.f + expf(-t1)),
                            1.f / (1.f + expf(-t2)), 1.f / (1.f + expf(-t3)));

        float4 c = wrv[it], d = urv[it], f = br4[j], h = hv[it];
        float r0 = 1.f / (1.f + expf(-lgr * (fwr * c.x + fur * d.x + fbr * f.x)));
        float r1 = 1.f / (1.f + expf(-lgr * (fwr * c.y + fur * d.y + fbr * f.y)));
        float r2 = 1.f / (1.f + expf(-lgr * (fwr * c.z + fur * d.z + fbr * f.z)));
        float r3 = 1.f / (1.f + expf(-lgr * (fwr * c.w + fur * d.w + fbr * f.w)));
        tv[it][0] = h.x * r0; tv[it][1] = h.y * r1; tv[it][2] = h.z * r2; tv[it][3] = h.w * r3;
        s[0] += tv[it][0] * tv[it][0] + tv[it][1] * tv[it][1] +
                tv[it][2] * tv[it][2] + tv[it][3] * tv[it][3];
    }
    block_reduce<1>(s);

    float ch = artanh_c(hn) / hn;
    float s2 = ch * ch * s[0];
    float nv = sqrtf(fmaxf(s2, MINN));
    float cpf = tanhf(nv) / nv * ch;
    float o2 = cpf * cpf * s[0];
    float on = sqrtf(fmaxf(o2, MINN));
    if (on > MAXN) { cpf *= MAXN / on; on = MAXN; }

#pragma unroll
    for (int it = 0; it < 2; it++) {
        int j = threadIdx.x + it * 256;
        float4 pv = make_float4(cpf * tv[it][0], cpf * tv[it][1], cpf * tv[it][2], cpf * tv[it][3]);
        uint2 hh;
        hi4h(pv, hh);
        size_t i4 = (size_t)row * (DD / 4) + j;
        ((uint2*)g_phi)[i4] = hh;
    }
    if (threadIdx.x == 0) g_rphn[row] = on;
}

// fused h_tilde transition + final mobius update -> out (hp = hidden*hsc)
__global__ void __launch_bounds__(256) ht_final_kernel(
    const __half* __restrict__ Wh, const __half* __restrict__ Ux, const float* __restrict__ bias,
    const float* __restrict__ hidden, float* __restrict__ out) {
    int row = blockIdx.x;
    const uint2* wr2 = (const uint2*)(Wh + (size_t)row * DD);
    const uint2* ur2 = (const uint2*)(Ux + (size_t)row * DD);
    const float4* bi4 = (const float4*)bias;
    const float4* hd4 = (const float4*)(hidden + (size_t)row * DD);
    const float4* z4 = (const float4*)(g_z + (size_t)row * DD);
    const float hsc = g_hsc[row];
    float4 wv[2], uv4[2], hv[2], zv[2];
    float v[6] = {0.f, 0.f, 0.f, 0.f, 0.f, 0.f};
#pragma unroll
    for (int it = 0; it < 2; it++) {
        int j = threadIdx.x + it * 256;
        float4 w = h4f(wr2[j]), u = h4f(ur2[j]), b = bi4[j];
        float4 hr = hd4[j];
        wv[it] = w; uv4[it] = u;
        hv[it] = make_float4(hr.x * hsc, hr.y * hsc, hr.z * hsc, hr.w * hsc);
        zv[it] = z4[j];
        v[0] += w.x * w.x + w.y * w.y + w.z * w.z + w.w * w.w;
        v[1] += u.x * u.x + u.y * u.y + u.z * u.z + u.w * u.w;
        v[2] += w.x * u.x + w.y * u.y + w.z * u.z + w.w * u.w;
        v[3] += w.x * b.x + w.y * b.y + w.z * b.z + w.w * b.w;
        v[4] += u.x * b.x + u.y * b.y + u.z * b.z + u.w * b.w;
        v[5] += b.x * b.x + b.y * b.y + b.z * b.z + b.w * b.w;
    }
    block_reduce<6>(v);

    float fw, fu, fb, f2;
    transition_coefs(v, g_rphn[row], g_xn[row], fw, fu, fb, f2);

    float tvv[2][4];
#pragma unroll
    for (int it = 0; it < 2; it++) {
        int j = threadIdx.x + it * 256;
        float4 w = wv[it], u = uv4[it], b = bi4[j];  // bias reload (L2)
        tvv[it][0] = fw * w.x + fu * u.x + fb * b.x;
        tvv[it][1] = fw * w.y + fu * u.y + fb * b.y;
        tvv[it][2] = fw * w.z + fu * u.z + fb * b.z;
        tvv[it][3] = fw * w.w + fu * u.w + fb * b.w;
    }

    float hn = g_hn[row];
    float u2 = hn * hn;

    float r2v[2] = {0.f, 0.f};
#pragma unroll
    for (int it = 0; it < 2; it++) {
        float4 h = hv[it];
        r2v[0] += h.x * tvv[it][0] + h.y * tvv[it][1] + h.z * tvv[it][2] + h.w * tvv[it][3];
        r2v[1] += tvv[it][0] * tvv[it][0] + tvv[it][1] * tvv[it][1] +
                  tvv[it][2] * tvv[it][2] + tvv[it][3] * tvv[it][3];
    }
    block_reduce<2>(r2v);

    float uv = -r2v[0], v2 = r2v[1];
    float a = 1.f + 2.f * uv + v2;
    float c = 1.f - u2;
    float den = fmaxf(1.f + 2.f * uv + u2 * v2, MINN);
    float mh = -a / den, mt = c / den;
    float m2 = mh * mh * u2 + 2.f * mh * mt * r2v[0] + mt * mt * r2v[1];
    {
        float n = sqrtf(fmaxf(m2, MINN));
        if (n > MAXN) { float f = MAXN / n; mh *= f; mt *= f; m2 *= f * f; }
    }
    float mn = sqrtf(fmaxf(m2, MINN));
    float cm = artanh_c(mn) / mn;

    float w2[2] = {0.f, 0.f};
#pragma unroll
    for (int it = 0; it < 2; it++) {
        float4 h = hv[it], z = zv[it];
        float m0 = mh * h.x + mt * tvv[it][0], m1 = mh * h.y + mt * tvv[it][1];
        float m2e = mh * h.z + mt * tvv[it][2], m3 = mh * h.w + mt * tvv[it][3];
        float p0 = z.x * m0, p1 = z.y * m1, p2 = z.z * m2e, p3 = z.w * m3;
        w2[0] += p0 * p0 + p1 * p1 + p2 * p2 + p3 * p3;
        w2[1] += p0 * h.x + p1 * h.y + p2 * h.z + p3 * h.w;
    }
    block_reduce<2>(w2);

    float sv2 = cm * cm * w2[0];
    float nv = sqrtf(fmaxf(sv2, MINN));
    float cp = tanhf(nv) / nv * cm;
    float p2 = cp * cp * w2[0];
    {
        float n = sqrtf(fmaxf(p2, MINN));
        if (n > MAXN) { float f = MAXN / n; cp *= f; p2 *= f * f; }
    }

    float uv2 = cp * w2[1];
    float A = 1.f + 2.f * uv2 + p2;
    float C = 1.f - u2;
    float den3 = fmaxf(1.f + 2.f * uv2 + u2 * p2, MINN);
    float chh = A / den3;
    float cpp = C * cp / den3;
    float o2 = chh * chh * u2 + 2.f * chh * cpp * w2[1] + cpp * cpp * w2[0];
    {
        float n = sqrtf(fmaxf(o2, MINN));
        if (n > MAXN) { float f = MAXN / n; chh *= f; cpp *= f; }
    }

    float4* o = (float4*)(out + (size_t)row * DD);
#pragma unroll
    for (int it = 0; it < 2; it++) {
        int j = threadIdx.x + it * 256;
        float4 h = hv[it], z = zv[it];
        float m0 = mh * h.x + mt * tvv[it][0], m1 = mh * h.y + mt * tvv[it][1];
        float m2e = mh * h.z + mt * tvv[it][2], m3 = mh * h.w + mt * tvv[it][3];
        o[j] = make_float4(chh * h.x + cpp * z.x * m0, chh * h.y + cpp * z.y * m1,
                           chh * h.z + cpp * z.z * m2e, chh * h.w + cpp * z.w * m3);
    }
}

// =================== launch ===================
extern "C" void kernel_launch(void* const* d_in, const int* in_sizes, int n_in,
                              void* d_out, int out_size) {
    (void)in_sizes; (void)n_in; (void)out_size;
    const float* hyp_x = (const float*)d_in[0];
    const float* hidden = (const float*)d_in[1];
    const float* w_z = (const float*)d_in[2];
    const float* w_r = (const float*)d_in[3];
    const float* w_h = (const float*)d_in[4];
    const float* u_z = (const float*)d_in[5];
    const float* u_r = (const float*)d_in[6];
    const float* b_z = (const float*)d_in[7];
    const float* b_r = (const float*)d_in[8];
    const float* b_h = (const float*)d_in[9];
    float* out = (float*)d_out;

    __half *G0, *G1, *G2, *G3, *G4;
    __half *xhi, *hhi, *phi, *whi;
    cudaGetSymbolAddress((void**)&G0, g_G0);
    cudaGetSymbolAddress((void**)&G1, g_G1);
    cudaGetSymbolAddress((void**)&G2, g_G2);
    cudaGetSymbolAddress((void**)&G3, g_G3);
    cudaGetSymbolAddress((void**)&G4, g_G4);
    cudaGetSymbolAddress((void**)&xhi, g_xhi);
    cudaGetSymbolAddress((void**)&hhi, g_hhi);
    cudaGetSymbolAddress((void**)&phi, g_phi);
    cudaGetSymbolAddress((void**)&whi, g_whi);

    static int smem_set = 0;
    if (!smem_set) {
        cudaFuncSetAttribute(mma_gate_kernel, cudaFuncAttributeMaxDynamicSharedMemorySize,
                             G_SMEM);
        smem_set = 1;
    }

    const size_t WSZ = (size_t)DD * DD;

    // 1. project inputs + fp16 convert (norms + per-row scale; no fp32 hp array)
    proj_norm_kernel<<<dim3(BB, 2), 256>>>(hyp_x, hidden);

    // 2. convert weights to fp16 (w_z, w_r, w_h, u_z, u_r)
    SplitArgs saw;
    saw.src[0] = w_z; saw.src[1] = w_r; saw.src[2] = w_h; saw.src[3] = u_z; saw.src[4] = u_r;
    split_w_kernel<<<dim3(DD * DD / 4 / 512, 5), 256>>>(saw);

    // 3. four independent fp16 GEMMs (fp16 outputs)
    GateArgs gg;
    gg.Ahi[0] = hhi; gg.Bhi[0] = whi + 0 * WSZ; gg.C[0] = G0;
    gg.Ahi[1] = hhi; gg.Bhi[1] = whi + 1 * WSZ; gg.C[1] = G1;
    gg.Ahi[2] = xhi; gg.Bhi[2] = whi + 3 * WSZ; gg.C[2] = G2;
    gg.Ahi[3] = xhi; gg.Bhi[3] = whi + 4 * WSZ; gg.C[3] = G3;
    mma_gate_kernel<<<dim3(16, 16, 4), 256, G_SMEM>>>(gg);

    // 4. fused z gate + r gate + r_point_h
    combine_zr_kernel<<<BB, 256>>>(G0, G2, b_z, G1, G3, b_r, hidden);

    // 5. G4 = rph @ w_h (fp16)
    GateArgs g4;
    g4.Ahi[0] = phi; g4.Bhi[0] = whi + 2 * WSZ; g4.C[0] = G4;
    g4.Ahi[1] = phi; g4.Bhi[1] = whi + 2 * WSZ; g4.C[1] = G4;
    g4.Ahi[2] = phi; g4.Bhi[2] = whi + 2 * WSZ; g4.C[2] = G4;
    g4.Ahi[3] = phi; g4.Bhi[3] = whi + 2 * WSZ; g4.C[3] = G4;
    mma_gate_kernel<<<dim3(16, 16, 1), 256, G_SMEM>>>(g4);

    // 6. fused h_tilde + final (reuses G3 = xp@u_r per reference)
    ht_final_kernel<<<BB, 256>>>(G4, G3, b_h, hidden, out);
}

// round 16
// speedup vs baseline: 1.5136x; 1.5136x over previous
#include <cuda_runtime.h>
#include <cuda_fp16.h>
#include <math.h>
#include <stdint.h>

#define BB 2048
#define DD 2048
#define MAXN (1.0f - 1e-5f)
#define MINN 1e-10f

// ---------------- scratch ----------------
__device__ float g_hp[BB * DD];
__device__ float g_xn[BB];
__device__ float g_hn[BB];
__device__ float g_rphn[BB];
__device__ __half g_G0[BB * DD];
__device__ __half g_G1[BB * DD];
__device__ __half g_G2[BB * DD];
__device__ __half g_G3[BB * DD];
__device__ __half g_G4[BB * DD];
__device__ float g_z[BB * DD];
__device__ __half g_xhi[BB * DD];
__device__ __half g_hhi[BB * DD];
__device__ __half g_phi[BB * DD];
__device__ __half g_whi[5 * DD * DD];

// =================== helpers ===================
__device__ __forceinline__ uint32_t smem_u32(const void* p) {
    uint32_t a;
    asm("{ .reg .u64 t; cvta.to.shared.u64 t, %1; cvt.u32.u64 %0, t; }" : "=r"(a) : "l"(p));
    return a;
}

__device__ __forceinline__ void hi4h(float4 v, uint2& h) {
    __half2 h0 = __floats2half2_rn(v.x, v.y);
    __half2 h1 = __floats2half2_rn(v.z, v.w);
    h.x = *reinterpret_cast<uint32_t*>(&h0);
    h.y = *reinterpret_cast<uint32_t*>(&h1);
}

__device__ __forceinline__ float4 h4f(uint2 u) {
    __half2 a = *reinterpret_cast<__half2*>(&u.x);
    __half2 b = *reinterpret_cast<__half2*>(&u.y);
    float2 fa = __half22float2(a), fb = __half22float2(b);
    return make_float4(fa.x, fa.y, fb.x, fb.y);
}

#define STS128U4(addr, v) \
    asm volatile("st.shared.v4.b32 [%0], {%1,%2,%3,%4};" \
                 :: "r"(addr), "r"((v).x), "r"((v).y), "r"((v).z), "r"((v).w) : "memory")

__device__ __forceinline__ void ldmatrix_x4(uint32_t* r, uint32_t addr) {
    asm volatile("ldmatrix.sync.aligned.m8n8.x4.shared.b16 {%0,%1,%2,%3}, [%4];"
                 : "=r"(r[0]), "=r"(r[1]), "=r"(r[2]), "=r"(r[3]) : "r"(addr));
}
__device__ __forceinline__ void ldmatrix_x4_t(uint32_t* r, uint32_t addr) {
    asm volatile("ldmatrix.sync.aligned.m8n8.x4.trans.shared.b16 {%0,%1,%2,%3}, [%4];"
                 : "=r"(r[0]), "=r"(r[1]), "=r"(r[2]), "=r"(r[3]) : "r"(addr));
}
__device__ __forceinline__ void mma16816(float* d, const uint32_t* a, uint32_t b0, uint32_t b1) {
    asm volatile(
        "mma.sync.aligned.m16n8k16.row.col.f32.f16.f16.f32 "
        "{%0,%1,%2,%3}, {%4,%5,%6,%7}, {%8,%9}, {%0,%1,%2,%3};"
        : "+f"(d[0]), "+f"(d[1]), "+f"(d[2]), "+f"(d[3])
        : "r"(a[0]), "r"(a[1]), "r"(a[2]), "r"(a[3]), "r"(b0), "r"(b1));
}

#define KC 64
#define NCH (DD / KC)
#define A_PITCH 144
#define B_PITCH 272

// =================== fp16 1-term GEMM (2 CTAs/SM, fp16 output) ===================
struct GateArgs {
    const __half* Ahi[4];
    const __half* Bhi[4];
    __half* C[4];
};
#define G_OF_B 18432u
#define G_STG 35840u
#define G_SMEM (2 * 35840)

__global__ void __launch_bounds__(256, 2) mma_gate_kernel(GateArgs ga) {
    extern __shared__ char smem[];
    const __half* __restrict__ Ahi = ga.Ahi[blockIdx.z];
    const __half* __restrict__ Bhi = ga.Bhi[blockIdx.z];
    __half* __restrict__ C = ga.C[blockIdx.z];
    const int m0 = blockIdx.y * 128, n0 = blockIdx.x * 128;
    const uint32_t sbase = smem_u32(smem);
    const int tid = threadIdx.x, wid = tid >> 5, lane = tid & 31;
    const int wm = wid >> 2, wn = wid & 3;

    float acc[4][4][4];
#pragma unroll
    for (int i = 0; i < 4; i++)
#pragma unroll
        for (int j = 0; j < 4; j++)
#pragma unroll
            for (int e = 0; e < 4; e++) acc[i][j][e] = 0.f;

    uint4 sa[4], sbv[4];

#pragma unroll
    for (int u = 0; u < 4; u++) {
        int unit = u * 256 + tid;
        int row = unit >> 3, col = unit & 7;
        sa[u] = *(const uint4*)(Ahi + (size_t)(m0 + row) * DD + col * 8);
        int brow = unit >> 4, bcol = unit & 15;
        sbv[u] = *(const uint4*)(Bhi + (size_t)brow * DD + n0 + bcol * 8);
    }
#pragma unroll
    for (int u = 0; u < 4; u++) {
        int unit = u * 256 + tid;
        int row = unit >> 3, col = unit & 7;
        STS128U4(sbase + (uint32_t)(row * A_PITCH + col * 16), sa[u]);
        int brow = unit >> 4, bcol = unit & 15;
        STS128U4(sbase + G_OF_B + (uint32_t)(brow * B_PITCH + bcol * 16), sbv[u]);
    }

    const int frow = lane & 15;
    const int fcol8 = (lane >> 4) * 8;

    for (int i = 0; i < NCH; i++) {
        const bool has_next = (i + 1) < NCH;
        if (has_next) {
            int kc = (i + 1) * KC;
#pragma unroll
            for (int u = 0; u < 4; u++) {
                int unit = u * 256 + tid;
                int row = unit >> 3, col = unit & 7;
                sa[u] = *(const uint4*)(Ahi + (size_t)(m0 + row) * DD + kc + col * 8);
                int brow = unit >> 4, bcol = unit & 15;
                sbv[u] = *(const uint4*)(Bhi + (size_t)(kc + brow) * DD + n0 + bcol * 8);
            }
        }
        __syncthreads();

        const uint32_t sb = sbase + (uint32_t)(i & 1) * G_STG;
#pragma unroll
        for (int ks = 0; ks < 4; ks++) {
            uint32_t a_h[4][4], b_h[2][4];
            uint32_t acol = (uint32_t)(ks * 16 + fcol8) * 2;
#pragma unroll
            for (int mt = 0; mt < 4; mt++)
                ldmatrix_x4(a_h[mt], sb + (uint32_t)((wm * 64 + mt * 16 + frow) * A_PITCH) + acol);
            uint32_t brow = (uint32_t)((ks * 16 + frow) * B_PITCH);
#pragma unroll
            for (int nh = 0; nh < 2; nh++)
                ldmatrix_x4_t(b_h[nh], sb + G_OF_B + brow + (uint32_t)(wn * 32 + nh * 16 + fcol8) * 2);
#pragma unroll
            for (int mt = 0; mt < 4; mt++)
#pragma unroll
                for (int j = 0; j < 4; j++) {
                    int nh = j >> 1, sbb = (j & 1) * 2;
                    mma16816(acc[mt][j], a_h[mt], b_h[nh][sbb], b_h[nh][sbb + 1]);
                }
        }

        if (has_next) {
            const uint32_t nb = sbase + (uint32_t)((i + 1) & 1) * G_STG;
#pragma unroll
            for (int u = 0; u < 4; u++) {
                int unit = u * 256 + tid;
                int row = unit >> 3, col = unit & 7;
                STS128U4(nb + (uint32_t)(row * A_PITCH + col * 16), sa[u]);
                int brow = unit >> 4, bcol = unit & 15;
                STS128U4(nb + G_OF_B + (uint32_t)(brow * B_PITCH + bcol * 16), sbv[u]);
            }
        }
    }

#pragma unroll
    for (int mt = 0; mt < 4; mt++)
#pragma unroll
        for (int j = 0; j < 4; j++) {
            int row = m0 + wm * 64 + mt * 16 + (lane >> 2);
            int col = n0 + wn * 32 + j * 8 + (lane & 3) * 2;
            __half2 p0 = __floats2half2_rn(acc[mt][j][0], acc[mt][j][1]);
            __half2 p1 = __floats2half2_rn(acc[mt][j][2], acc[mt][j][3]);
            *(__half2*)(C + (size_t)row * DD + col) = p0;
            *(__half2*)(C + (size_t)(row + 8) * DD + col) = p1;
        }
}

// =================== elementwise kernels ===================
template <int NV>
__device__ __forceinline__ void block_reduce(float (&v)[NV]) {
    __shared__ float sm[NV * 8];
    __syncthreads();
    int lane = threadIdx.x & 31, w = threadIdx.x >> 5;
#pragma unroll
    for (int i = 0; i < NV; i++) {
        float x = v[i];
#pragma unroll
        for (int o = 16; o > 0; o >>= 1) x += __shfl_down_sync(0xffffffffu, x, o);
        if (lane == 0) sm[i * 8 + w] = x;
    }
    __syncthreads();
    if (threadIdx.x == 0) {
#pragma unroll
        for (int i = 0; i < NV; i++) {
            float s = 0.f;
#pragma unroll
            for (int j = 0; j < 8; j++) s += sm[i * 8 + j];
            sm[i * 8] = s;
        }
    }
    __syncthreads();
#pragma unroll
    for (int i = 0; i < NV; i++) v[i] = sm[i * 8];
}

__device__ __forceinline__ float artanh_c(float x) { return atanhf(fminf(x, MAXN)); }

__device__ __forceinline__ void proj_coef(float& coef, float& s2) {
    float n = sqrtf(fmaxf(s2, MINN));
    if (n > MAXN) {
        float f = MAXN / n;
        coef *= f;
        s2 *= f * f;
    }
}

__device__ __forceinline__ void transition_coefs(const float* v, float hn, float xn,
                                                 float& fw, float& fu, float& fb, float& f2) {
    float Mw = sqrtf(fmaxf(v[0], MINN));
    float cu = tanhf(Mw / hn * artanh_c(hn)) / Mw;
    float su = cu * cu * v[0];
    proj_coef(cu, su);

    float Mu = sqrtf(fmaxf(v[1], MINN));
    float cv = tanhf(Mu / xn * artanh_c(xn)) / Mu;
    float sv = cv * cv * v[1];
    proj_coef(cv, sv);

    float uv = cu * cv * v[2];
    float a = 1.f + 2.f * uv + sv;
    float c = 1.f - su;
    float den = fmaxf(1.f + 2.f * uv + su * sv, MINN);
    float aw = a * cu / den, au = c * cv / den;
    float q2 = aw * aw * v[0] + 2.f * aw * au * v[2] + au * au * v[1];
    {
        float n = sqrtf(fmaxf(q2, MINN));
        if (n > MAXN) { float f = MAXN / n; aw *= f; au *= f; q2 *= f * f; }
    }

    float qb = aw * v[3] + au * v[4];
    float b2 = v[5];
    float A2 = 1.f + 2.f * qb + b2;
    float C2 = 1.f - q2;
    float den2 = fmaxf(1.f + 2.f * qb + q2 * b2, MINN);
    fw = A2 * aw / den2; fu = A2 * au / den2; fb = C2 / den2;
    f2 = fw * fw * v[0] + fu * fu * v[1] + fb * fb * v[5] +
         2.f * fw * fu * v[2] + 2.f * fw * fb * v[3] + 2.f * fu * fb * v[4];
    {
        float n = sqrtf(fmaxf(f2, MINN));
        if (n > MAXN) { float f = MAXN / n; fw *= f; fu *= f; fb *= f; f2 *= f * f; }
    }
}

__global__ void __launch_bounds__(256) proj_norm_kernel(const float* __restrict__ hx,
                                                        const float* __restrict__ hd) {
    int row = blockIdx.x;
    int ish = blockIdx.y;
    const float* src = ish ? hd : hx;
    const float4* p = (const float4*)(src + (size_t)row * DD);
    float4 a = p[threadIdx.x], b = p[threadIdx.x + 256];
    float acc[1] = {a.x * a.x + a.y * a.y + a.z * a.z + a.w * a.w +
                    b.x * b.x + b.y * b.y + b.z * b.z + b.w * b.w};
    block_reduce<1>(acc);
    float n = sqrtf(fmaxf(acc[0], MINN));
    float sc = (n > MAXN) ? (MAXN / n) : 1.f;
    float4 va = make_float4(a.x * sc, a.y * sc, a.z * sc, a.w * sc);
    float4 vb = make_float4(b.x * sc, b.y * sc, b.z * sc, b.w * sc);
    uint2 ha, hb;
    hi4h(va, ha);
    hi4h(vb, hb);
    size_t i0 = (size_t)row * (DD / 4) + threadIdx.x;
    size_t i1 = i0 + 256;
    if (ish) {
        ((float4*)g_hp)[i0] = va;
        ((float4*)g_hp)[i1] = vb;
        ((uint2*)g_hhi)[i0] = ha; ((uint2*)g_hhi)[i1] = hb;
        if (threadIdx.x == 0) g_hn[row] = fminf(n, MAXN);
    } else {
        ((uint2*)g_xhi)[i0] = ha; ((uint2*)g_xhi)[i1] = hb;
        if (threadIdx.x == 0) g_xn[row] = fminf(n, MAXN);
    }
}

struct SplitArgs { const float* src[5]; };
__global__ void __launch_bounds__(256) split_w_kernel(SplitArgs saw) {
    int w = blockIdx.y;
    size_t base = (size_t)blockIdx.x * 512 + threadIdx.x;
#pragma unroll
    for (int it = 0; it < 2; it++) {
        size_t i4 = base + it * 256;
        float4 v = ((const float4*)saw.src[w])[i4];
        size_t o = (size_t)w * (DD * DD / 4) + i4;
        uint2 h;
        hi4h(v, h);
        ((uint2*)g_whi)[o] = h;
    }
}

// fused: z gate -> g_z (fp32), r gate + r_point_h -> phi + rphn  (G arrays fp16)
__global__ void __launch_bounds__(256) combine_zr_kernel(
    const __half* __restrict__ G0, const __half* __restrict__ G2, const float* __restrict__ bz,
    const __half* __restrict__ G1, const __half* __restrict__ G3, const float* __restrict__ br) {
    int row = blockIdx.x;
    const uint2* wz2 = (const uint2*)(G0 + (size_t)row * DD);
    const uint2* uz2 = (const uint2*)(G2 + (size_t)row * DD);
    const uint2* wr2 = (const uint2*)(G1 + (size_t)row * DD);
    const uint2* ur2 = (const uint2*)(G3 + (size_t)row * DD);
    const float4* bz4 = (const float4*)bz;
    const float4* br4 = (const float4*)br;
    const float4* hp4 = (const float4*)(g_hp + (size_t)row * DD);

    float4 wrv[2], urv[2], hv[2];
    float v[12];
#pragma unroll
    for (int q = 0; q < 12; q++) v[q] = 0.f;
#pragma unroll
    for (int it = 0; it < 2; it++) {
        int j = threadIdx.x + it * 256;
        float4 a = h4f(wz2[j]), b = h4f(uz2[j]), c = h4f(wr2[j]), d = h4f(ur2[j]);
        float4 e = bz4[j], f = br4[j];
        wrv[it] = c; urv[it] = d; hv[it] = hp4[j];
        v[0] += a.x * a.x + a.y * a.y + a.z * a.z + a.w * a.w;
        v[1] += b.x * b.x + b.y * b.y + b.z * b.z + b.w * b.w;
        v[2] += a.x * b.x + a.y * b.y + a.z * b.z + a.w * b.w;
        v[3] += a.x * e.x + a.y * e.y + a.z * e.z + a.w * e.w;
        v[4] += b.x * e.x + b.y * e.y + b.z * e.z + b.w * e.w;
        v[5] += e.x * e.x + e.y * e.y + e.z * e.z + e.w * e.w;
        v[6] += c.x * c.x + c.y * c.y + c.z * c.z + c.w * c.w;
        v[7] += d.x * d.x + d.y * d.y + d.z * d.z + d.w * d.w;
        v[8] += c.x * d.x + c.y * d.y + c.z * d.z + c.w * d.w;
        v[9] += c.x * f.x + c.y * f.y + c.z * f.z + c.w * f.w;
        v[10] += d.x * f.x + d.y * f.y + d.z * f.z + d.w * f.w;
        v[11] += f.x * f.x + f.y * f.y + f.z * f.z + f.w * f.w;
    }
    block_reduce<12>(v);

    float hn = g_hn[row], xn = g_xn[row];

    float fwz, fuz, fbz, f2z;
    transition_coefs(&v[0], hn, xn, fwz, fuz, fbz, f2z);
    float fnz = sqrtf(fmaxf(f2z, MINN));
    float lgz = artanh_c(fnz) / fnz;

    float fwr, fur, fbr, f2r;
    transition_coefs(&v[6], hn, xn, fwr, fur, fbr, f2r);
    float fnr = sqrtf(fmaxf(f2r, MINN));
    float lgr = artanh_c(fnr) / fnr;

    float tv[2][4];
    float s[1] = {0.f};
    float4* oz = (float4*)(g_z + (size_t)row * DD);
#pragma unroll
    for (int it = 0; it < 2; it++) {
        int j = threadIdx.x + it * 256;
        float4 a = h4f(wz2[j]), b = h4f(uz2[j]);
        float4 e = bz4[j];
        float t0 = lgz * (fwz * a.x + fuz * b.x + fbz * e.x);
        float t1 = lgz * (fwz * a.y + fuz * b.y + fbz * e.y);
        float t2 = lgz * (fwz * a.z + fuz * b.z + fbz * e.z);
        float t3 = lgz * (fwz * a.w + fuz * b.w + fbz * e.w);
        oz[j] = make_float4(1.f / (1.f + expf(-t0)), 1.f / (1.f + expf(-t1)),
                            1.f / (1.f + expf(-t2)), 1.f / (1.f + expf(-t3)));

        float4 c = wrv[it], d = urv[it], f = br4[j], h = hv[it];
        float r0 = 1.f / (1.f + expf(-lgr * (fwr * c.x + fur * d.x + fbr * f.x)));
        float r1 = 1.f / (1.f + expf(-lgr * (fwr * c.y + fur * d.y + fbr * f.y)));
        float r2 = 1.f / (1.f + expf(-lgr * (fwr * c.z + fur * d.z + fbr * f.z)));
        float r3 = 1.f / (1.f + expf(-lgr * (fwr * c.w + fur * d.w + fbr * f.w)));
        tv[it][0] = h.x * r0; tv[it][1] = h.y * r1; tv[it][2] = h.z * r2; tv[it][3] = h.w * r3;
        s[0] += tv[it][0] * tv[it][0] + tv[it][1] * tv[it][1] +
                tv[it][2] * tv[it][2] + tv[it][3] * tv[it][3];
    }
    block_reduce<1>(s);

    float ch = artanh_c(hn) / hn;
    float s2 = ch * ch * s[0];
    float nv = sqrtf(fmaxf(s2, MINN));
    float cpf = tanhf(nv) / nv * ch;
    float o2 = cpf * cpf * s[0];
    float on = sqrtf(fmaxf(o2, MINN));
    if (on > MAXN) { cpf *= MAXN / on; on = MAXN; }

#pragma unroll
    for (int it = 0; it < 2; it++) {
        int j = threadIdx.x + it * 256;
        float4 pv = make_float4(cpf * tv[it][0], cpf * tv[it][1], cpf * tv[it][2], cpf * tv[it][3]);
        uint2 hh;
        hi4h(pv, hh);
        size_t i4 = (size_t)row * (DD / 4) + j;
        ((uint2*)g_phi)[i4] = hh;
    }
    if (threadIdx.x == 0) g_rphn[row] = on;
}

// fused h_tilde transition + final mobius update -> out  (G arrays fp16)
__global__ void __launch_bounds__(256) ht_final_kernel(
    const __half* __restrict__ Wh, const __half* __restrict__ Ux, const float* __restrict__ bias,
    float* __restrict__ out) {
    int row = blockIdx.x;
    const uint2* wr2 = (const uint2*)(Wh + (size_t)row * DD);
    const uint2* ur2 = (const uint2*)(Ux + (size_t)row * DD);
    const float4* bi4 = (const float4*)bias;
    const float4* hp4 = (const float4*)(g_hp + (size_t)row * DD);
    const float4* z4 = (const float4*)(g_z + (size_t)row * DD);
    float4 wv[2], uv4[2], hv[2], zv[2];
    float v[6] = {0.f, 0.f, 0.f, 0.f, 0.f, 0.f};
#pragma unroll
    for (int it = 0; it < 2; it++) {
        int j = threadIdx.x + it * 256;
        float4 w = h4f(wr2[j]), u = h4f(ur2[j]), b = bi4[j];
        wv[it] = w; uv4[it] = u; hv[it] = hp4[j]; zv[it] = z4[j];
        v[0] += w.x * w.x + w.y * w.y + w.z * w.z + w.w * w.w;
        v[1] += u.x * u.x + u.y * u.y + u.z * u.z + u.w * u.w;
        v[2] += w.x * u.x + w.y * u.y + w.z * u.z + w.w * u.w;
        v[3] += w.x * b.x + w.y * b.y + w.z * b.z + w.w * b.w;
        v[4] += u.x * b.x + u.y * b.y + u.z * b.z + u.w * b.w;
        v[5] += b.x * b.x + b.y * b.y + b.z * b.z + b.w * b.w;
    }
    block_reduce<6>(v);

    float fw, fu, fb, f2;
    transition_coefs(v, g_rphn[row], g_xn[row], fw, fu, fb, f2);

    float tvv[2][4];
#pragma unroll
    for (int it = 0; it < 2; it++) {
        int j = threadIdx.x + it * 256;
        float4 w = wv[it], u = uv4[it], b = bi4[j];  // bias reload (L2)
        tvv[it][0] = fw * w.x + fu * u.x + fb * b.x;
        tvv[it][1] = fw * w.y + fu * u.y + fb * b.y;
        tvv[it][2] = fw * w.z + fu * u.z + fb * b.z;
        tvv[it][3] = fw * w.w + fu * u.w + fb * b.w;
    }

    float hn = g_hn[row];
    float u2 = hn * hn;

    float r2v[2] = {0.f, 0.f};
#pragma unroll
    for (int it = 0; it < 2; it++) {
        float4 h = hv[it];
        r2v[0] += h.x * tvv[it][0] + h.y * tvv[it][1] + h.z * tvv[it][2] + h.w * tvv[it][3];
        r2v[1] += tvv[it][0] * tvv[it][0] + tvv[it][1] * tvv[it][1] +
                  tvv[it][2] * tvv[it][2] + tvv[it][3] * tvv[it][3];
    }
    block_reduce<2>(r2v);

    float uv = -r2v[0], v2 = r2v[1];
    float a = 1.f + 2.f * uv + v2;
    float c = 1.f - u2;
    float den = fmaxf(1.f + 2.f * uv + u2 * v2, MINN);
    float mh = -a / den, mt = c / den;
    float m2 = mh * mh * u2 + 2.f * mh * mt * r2v[0] + mt * mt * r2v[1];
    {
        float n = sqrtf(fmaxf(m2, MINN));
        if (n > MAXN) { float f = MAXN / n; mh *= f; mt *= f; m2 *= f * f; }
    }
    float mn = sqrtf(fmaxf(m2, MINN));
    float cm = artanh_c(mn) / mn;

    float w2[2] = {0.f, 0.f};
#pragma unroll
    for (int it = 0; it < 2; it++) {
        float4 h = hv[it], z = zv[it];
        float m0 = mh * h.x + mt * tvv[it][0], m1 = mh * h.y + mt * tvv[it][1];
        float m2e = mh * h.z + mt * tvv[it][2], m3 = mh * h.w + mt * tvv[it][3];
        float p0 = z.x * m0, p1 = z.y * m1, p2 = z.z * m2e, p3 = z.w * m3;
        w2[0] += p0 * p0 + p1 * p1 + p2 * p2 + p3 * p3;
        w2[1] += p0 * h.x + p1 * h.y + p2 * h.z + p3 * h.w;
    }
    block_reduce<2>(w2);

    float sv2 = cm * cm * w2[0];
    float nv = sqrtf(fmaxf(sv2, MINN));
    float cp = tanhf(nv) / nv * cm;
    float p2 = cp * cp * w2[0];
    {
        float n = sqrtf(fmaxf(p2, MINN));
        if (n > MAXN) { float f = MAXN / n; cp *= f; p2 *= f * f; }
    }

    float uv2 = cp * w2[1];
    float A = 1.f + 2.f * uv2 + p2;
    float C = 1.f - u2;
    float den3 = fmaxf(1.f + 2.f * uv2 + u2 * p2, MINN);
    float chh = A / den3;
    float cpp = C * cp / den3;
    float o2 = chh * chh * u2 + 2.f * chh * cpp * w2[1] + cpp * cpp * w2[0];
    {
        float n = sqrtf(fmaxf(o2, MINN));
        if (n > MAXN) { float f = MAXN / n; chh *= f; cpp *= f; }
    }

    float4* o = (float4*)(out + (size_t)row * DD);
#pragma unroll
    for (int it = 0; it < 2; it++) {
        int j = threadIdx.x + it * 256;
        float4 h = hv[it], z = zv[it];
        float m0 = mh * h.x + mt * tvv[it][0], m1 = mh * h.y + mt * tvv[it][1];
        float m2e = mh * h.z + mt * tvv[it][2], m3 = mh * h.w + mt * tvv[it][3];
        o[j] = make_float4(chh * h.x + cpp * z.x * m0, chh * h.y + cpp * z.y * m1,
                           chh * h.z + cpp * z.z * m2e, chh * h.w + cpp * z.w * m3);
    }
}

// =================== launch ===================
extern "C" void kernel_launch(void* const* d_in, const int* in_sizes, int n_in,
                              void* d_out, int out_size) {
    (void)in_sizes; (void)n_in; (void)out_size;
    const float* hyp_x = (const float*)d_in[0];
    const float* hidden = (const float*)d_in[1];
    const float* w_z = (const float*)d_in[2];
    const float* w_r = (const float*)d_in[3];
    const float* w_h = (const float*)d_in[4];
    const float* u_z = (const float*)d_in[5];
    const float* u_r = (const float*)d_in[6];
    const float* b_z = (const float*)d_in[7];
    const float* b_r = (const float*)d_in[8];
    const float* b_h = (const float*)d_in[9];
    float* out = (float*)d_out;

    __half *G0, *G1, *G2, *G3, *G4;
    __half *xhi, *hhi, *phi, *whi;
    cudaGetSymbolAddress((void**)&G0, g_G0);
    cudaGetSymbolAddress((void**)&G1, g_G1);
    cudaGetSymbolAddress((void**)&G2, g_G2);
    cudaGetSymbolAddress((void**)&G3, g_G3);
    cudaGetSymbolAddress((void**)&G4, g_G4);
    cudaGetSymbolAddress((void**)&xhi, g_xhi);
    cudaGetSymbolAddress((void**)&hhi, g_hhi);
    cudaGetSymbolAddress((void**)&phi, g_phi);
    cudaGetSymbolAddress((void**)&whi, g_whi);

    static int smem_set = 0;
    if (!smem_set) {
        cudaFuncSetAttribute(mma_gate_kernel, cudaFuncAttributeMaxDynamicSharedMemorySize,
                             G_SMEM);
        smem_set = 1;
    }

    const size_t WSZ = (size_t)DD * DD;

    // 1. project inputs + fp16 convert
    proj_norm_kernel<<<dim3(BB, 2), 256>>>(hyp_x, hidden);

    // 2. convert weights to fp16 (w_z, w_r, w_h, u_z, u_r)
    SplitArgs saw;
    saw.src[0] = w_z; saw.src[1] = w_r; saw.src[2] = w_h; saw.src[3] = u_z; saw.src[4] = u_r;
    split_w_kernel<<<dim3(DD * DD / 4 / 512, 5), 256>>>(saw);

    // 3. four independent fp16 GEMMs (fp16 outputs)
    GateArgs gg;
    gg.Ahi[0] = hhi; gg.Bhi[0] = whi + 0 * WSZ; gg.C[0] = G0;
    gg.Ahi[1] = hhi; gg.Bhi[1] = whi + 1 * WSZ; gg.C[1] = G1;
    gg.Ahi[2] = xhi; gg.Bhi[2] = whi + 3 * WSZ; gg.C[2] = G2;
    gg.Ahi[3] = xhi; gg.Bhi[3] = whi + 4 * WSZ; gg.C[3] = G3;
    mma_gate_kernel<<<dim3(16, 16, 4), 256, G_SMEM>>>(gg);

    // 4. fused z gate + r gate + r_point_h (z fp32, phi fp16)
    combine_zr_kernel<<<BB, 256>>>(G0, G2, b_z, G1, G3, b_r);

    // 5. G4 = rph @ w_h (fp16)
    GateArgs g4;
    g4.Ahi[0] = phi; g4.Bhi[0] = whi + 2 * WSZ; g4.C[0] = G4;
    g4.Ahi[1] = phi; g4.Bhi[1] = whi + 2 * WSZ; g4.C[1] = G4;
    g4.Ahi[2] = phi; g4.Bhi[2] = whi + 2 * WSZ; g4.C[2] = G4;
    g4.Ahi[3] = phi; g4.Bhi[3] = whi + 2 * WSZ; g4.C[3] = G4;
    mma_gate_kernel<<<dim3(16, 16, 1), 256, G_SMEM>>>(g4);

    // 6. fused h_tilde + final (reuses G3 = xp@u_r per reference)
    ht_final_kernel<<<BB, 256>>>(G4, G3, b_h, out);
}

// round 17
// speedup vs baseline: 1.5503x; 1.0242x over previous
#include <cuda_runtime.h>
#include <cuda_fp16.h>
#include <math.h>
#include <stdint.h>

#define BB 2048
#define DD 2048
#define MAXN (1.0f - 1e-5f)
#define MINN 1e-10f

// ---------------- scratch ----------------
__device__ float g_hp[BB * DD];
__device__ float g_xn[BB];
__device__ float g_hn[BB];
__device__ float g_rphn[BB];
__device__ __half g_G0[BB * DD];
__device__ __half g_G1[BB * DD];
__device__ __half g_G2[BB * DD];
__device__ __half g_G3[BB * DD];
__device__ __half g_G4[BB * DD];
__device__ float g_z[BB * DD];
__device__ __half g_xhi[BB * DD];
__device__ __half g_hhi[BB * DD];
__device__ __half g_phi[BB * DD];
__device__ __half g_whi[5 * DD * DD];

// =================== helpers ===================
__device__ __forceinline__ uint32_t smem_u32(const void* p) {
    uint32_t a;
    asm("{ .reg .u64 t; cvta.to.shared.u64 t, %1; cvt.u32.u64 %0, t; }" : "=r"(a) : "l"(p));
    return a;
}

__device__ __forceinline__ void hi4h(float4 v, uint2& h) {
    __half2 h0 = __floats2half2_rn(v.x, v.y);
    __half2 h1 = __floats2half2_rn(v.z, v.w);
    h.x = *reinterpret_cast<uint32_t*>(&h0);
    h.y = *reinterpret_cast<uint32_t*>(&h1);
}

__device__ __forceinline__ float4 h4f(uint2 u) {
    __half2 a = *reinterpret_cast<__half2*>(&u.x);
    __half2 b = *reinterpret_cast<__half2*>(&u.y);
    float2 fa = __half22float2(a), fb = __half22float2(b);
    return make_float4(fa.x, fa.y, fb.x, fb.y);
}

#define STS128U4(addr, v) \
    asm volatile("st.shared.v4.b32 [%0], {%1,%2,%3,%4};" \
                 :: "r"(addr), "r"((v).x), "r"((v).y), "r"((v).z), "r"((v).w) : "memory")

__device__ __forceinline__ void ldmatrix_x4(uint32_t* r, uint32_t addr) {
    asm volatile("ldmatrix.sync.aligned.m8n8.x4.shared.b16 {%0,%1,%2,%3}, [%4];"
                 : "=r"(r[0]), "=r"(r[1]), "=r"(r[2]), "=r"(r[3]) : "r"(addr));
}
__device__ __forceinline__ void ldmatrix_x4_t(uint32_t* r, uint32_t addr) {
    asm volatile("ldmatrix.sync.aligned.m8n8.x4.trans.shared.b16 {%0,%1,%2,%3}, [%4];"
                 : "=r"(r[0]), "=r"(r[1]), "=r"(r[2]), "=r"(r[3]) : "r"(addr));
}
__device__ __forceinline__ void mma16816(float* d, const uint32_t* a, uint32_t b0, uint32_t b1) {
    asm volatile(
        "mma.sync.aligned.m16n8k16.row.col.f32.f16.f16.f32 "
        "{%0,%1,%2,%3}, {%4,%5,%6,%7}, {%8,%9}, {%0,%1,%2,%3};"
        : "+f"(d[0]), "+f"(d[1]), "+f"(d[2]), "+f"(d[3])
        : "r"(a[0]), "r"(a[1]), "r"(a[2]), "r"(a[3]), "r"(b0), "r"(b1));
}

#define KC 64
#define NCH (DD / KC)
#define A_PITCH 144
#define B_PITCH 272

// =================== fp16 1-term GEMM (2 CTAs/SM, fp16 output) ===================
struct GateArgs {
    const __half* Ahi[4];
    const __half* Bhi[4];
    __half* C[4];
};
#define G_OF_B 18432u
#define G_STG 35840u
#define G_SMEM (2 * 35840)

__global__ void __launch_bounds__(256, 2) mma_gate_kernel(GateArgs ga) {
    extern __shared__ char smem[];
    const __half* __restrict__ Ahi = ga.Ahi[blockIdx.z];
    const __half* __restrict__ Bhi = ga.Bhi[blockIdx.z];
    __half* __restrict__ C = ga.C[blockIdx.z];
    const int m0 = blockIdx.y * 128, n0 = blockIdx.x * 128;
    const uint32_t sbase = smem_u32(smem);
    const int tid = threadIdx.x, wid = tid >> 5, lane = tid & 31;
    const int wm = wid >> 2, wn = wid & 3;

    float acc[4][4][4];
#pragma unroll
    for (int i = 0; i < 4; i++)
#pragma unroll
        for (int j = 0; j < 4; j++)
#pragma unroll
            for (int e = 0; e < 4; e++) acc[i][j][e] = 0.f;

    uint4 sa[4], sbv[4];

#pragma unroll
    for (int u = 0; u < 4; u++) {
        int unit = u * 256 + tid;
        int row = unit >> 3, col = unit & 7;
        sa[u] = *(const uint4*)(Ahi + (size_t)(m0 + row) * DD + col * 8);
        int brow = unit >> 4, bcol = unit & 15;
        sbv[u] = *(const uint4*)(Bhi + (size_t)brow * DD + n0 + bcol * 8);
    }
#pragma unroll
    for (int u = 0; u < 4; u++) {
        int unit = u * 256 + tid;
        int row = unit >> 3, col = unit & 7;
        STS128U4(sbase + (uint32_t)(row * A_PITCH + col * 16), sa[u]);
        int brow = unit >> 4, bcol = unit & 15;
        STS128U4(sbase + G_OF_B + (uint32_t)(brow * B_PITCH + bcol * 16), sbv[u]);
    }

    const int frow = lane & 15;
    const int fcol8 = (lane >> 4) * 8;

    for (int i = 0; i < NCH; i++) {
        const bool has_next = (i + 1) < NCH;
        if (has_next) {
            int kc = (i + 1) * KC;
#pragma unroll
            for (int u = 0; u < 4; u++) {
                int unit = u * 256 + tid;
                int row = unit >> 3, col = unit & 7;
                sa[u] = *(const uint4*)(Ahi + (size_t)(m0 + row) * DD + kc + col * 8);
                int brow = unit >> 4, bcol = unit & 15;
                sbv[u] = *(const uint4*)(Bhi + (size_t)(kc + brow) * DD + n0 + bcol * 8);
            }
        }
        __syncthreads();

        const uint32_t sb = sbase + (uint32_t)(i & 1) * G_STG;
#pragma unroll
        for (int ks = 0; ks < 4; ks++) {
            uint32_t a_h[4][4], b_h[2][4];
            uint32_t acol = (uint32_t)(ks * 16 + fcol8) * 2;
#pragma unroll
            for (int mt = 0; mt < 4; mt++)
                ldmatrix_x4(a_h[mt], sb + (uint32_t)((wm * 64 + mt * 16 + frow) * A_PITCH) + acol);
            uint32_t brow = (uint32_t)((ks * 16 + frow) * B_PITCH);
#pragma unroll
            for (int nh = 0; nh < 2; nh++)
                ldmatrix_x4_t(b_h[nh], sb + G_OF_B + brow + (uint32_t)(wn * 32 + nh * 16 + fcol8) * 2);
#pragma unroll
            for (int mt = 0; mt < 4; mt++)
#pragma unroll
                for (int j = 0; j < 4; j++) {
                    int nh = j >> 1, sbb = (j & 1) * 2;
                    mma16816(acc[mt][j], a_h[mt], b_h[nh][sbb], b_h[nh][sbb + 1]);
                }
        }

        if (has_next) {
            const uint32_t nb = sbase + (uint32_t)((i + 1) & 1) * G_STG;
#pragma unroll
            for (int u = 0; u < 4; u++) {
                int unit = u * 256 + tid;
                int row = unit >> 3, col = unit & 7;
                STS128U4(nb + (uint32_t)(row * A_PITCH + col * 16), sa[u]);
                int brow = unit >> 4, bcol = unit & 15;
                STS128U4(nb + G_OF_B + (uint32_t)(brow * B_PITCH + bcol * 16), sbv[u]);
            }
        }
    }

#pragma unroll
    for (int mt = 0; mt < 4; mt++)
#pragma unroll
        for (int j = 0; j < 4; j++) {
            int row = m0 + wm * 64 + mt * 16 + (lane >> 2);
            int col = n0 + wn * 32 + j * 8 + (lane & 3) * 2;
            __half2 p0 = __floats2half2_rn(acc[mt][j][0], acc[mt][j][1]);
            __half2 p1 = __floats2half2_rn(acc[mt][j][2], acc[mt][j][3]);
            *(__half2*)(C + (size_t)row * DD + col) = p0;
            *(__half2*)(C + (size_t)(row + 8) * DD + col) = p1;
        }
}

// =================== elementwise kernels ===================
template <int NV>
__device__ __forceinline__ void block_reduce(float (&v)[NV]) {
    __shared__ float sm[NV * 8];
    __syncthreads();
    int lane = threadIdx.x & 31, w = threadIdx.x >> 5;
#pragma unroll
    for (int i = 0; i < NV; i++) {
        float x = v[i];
#pragma unroll
        for (int o = 16; o > 0; o >>= 1) x += __shfl_down_sync(0xffffffffu, x, o);
        if (lane == 0) sm[i * 8 + w] = x;
    }
    __syncthreads();
    if (threadIdx.x == 0) {
#pragma unroll
        for (int i = 0; i < NV; i++) {
            float s = 0.f;
#pragma unroll
            for (int j = 0; j < 8; j++) s += sm[i * 8 + j];
            sm[i * 8] = s;
        }
    }
    __syncthreads();
#pragma unroll
    for (int i = 0; i < NV; i++) v[i] = sm[i * 8];
}

__device__ __forceinline__ float artanh_c(float x) { return atanhf(fminf(x, MAXN)); }

__device__ __forceinline__ void proj_coef(float& coef, float& s2) {
    float n = sqrtf(fmaxf(s2, MINN));
    if (n > MAXN) {
        float f = MAXN / n;
        coef *= f;
        s2 *= f * f;
    }
}

__device__ __forceinline__ void transition_coefs(const float* v, float hn, float xn,
                                                 float& fw, float& fu, float& fb, float& f2) {
    float Mw = sqrtf(fmaxf(v[0], MINN));
    float cu = tanhf(Mw / hn * artanh_c(hn)) / Mw;
    float su = cu * cu * v[0];
    proj_coef(cu, su);

    float Mu = sqrtf(fmaxf(v[1], MINN));
    float cv = tanhf(Mu / xn * artanh_c(xn)) / Mu;
    float sv = cv * cv * v[1];
    proj_coef(cv, sv);

    float uv = cu * cv * v[2];
    float a = 1.f + 2.f * uv + sv;
    float c = 1.f - su;
    float den = fmaxf(1.f + 2.f * uv + su * sv, MINN);
    float aw = a * cu / den, au = c * cv / den;
    float q2 = aw * aw * v[0] + 2.f * aw * au * v[2] + au * au * v[1];
    {
        float n = sqrtf(fmaxf(q2, MINN));
        if (n > MAXN) { float f = MAXN / n; aw *= f; au *= f; q2 *= f * f; }
    }

    float qb = aw * v[3] + au * v[4];
    float b2 = v[5];
    float A2 = 1.f + 2.f * qb + b2;
    float C2 = 1.f - q2;
    float den2 = fmaxf(1.f + 2.f * qb + q2 * b2, MINN);
    fw = A2 * aw / den2; fu = A2 * au / den2; fb = C2 / den2;
    f2 = fw * fw * v[0] + fu * fu * v[1] + fb * fb * v[5] +
         2.f * fw * fu * v[2] + 2.f * fw * fb * v[3] + 2.f * fu * fb * v[4];
    {
        float n = sqrtf(fmaxf(f2, MINN));
        if (n > MAXN) { float f = MAXN / n; fw *= f; fu *= f; fb *= f; f2 *= f * f; }
    }
}

__global__ void __launch_bounds__(256) proj_norm_kernel(const float* __restrict__ hx,
                                                        const float* __restrict__ hd) {
    int row = blockIdx.x;
    int ish = blockIdx.y;
    const float* src = ish ? hd : hx;
    const float4* p = (const float4*)(src + (size_t)row * DD);
    float4 a = p[threadIdx.x], b = p[threadIdx.x + 256];
    float acc[1] = {a.x * a.x + a.y * a.y + a.z * a.z + a.w * a.w +
                    b.x * b.x + b.y * b.y + b.z * b.z + b.w * b.w};
    block_reduce<1>(acc);
    float n = sqrtf(fmaxf(acc[0], MINN));
    float sc = (n > MAXN) ? (MAXN / n) : 1.f;
    float4 va = make_float4(a.x * sc, a.y * sc, a.z * sc, a.w * sc);
    float4 vb = make_float4(b.x * sc, b.y * sc, b.z * sc, b.w * sc);
    uint2 ha, hb;
    hi4h(va, ha);
    hi4h(vb, hb);
    size_t i0 = (size_t)row * (DD / 4) + threadIdx.x;
    size_t i1 = i0 + 256;
    if (ish) {
        ((float4*)g_hp)[i0] = va;
        ((float4*)g_hp)[i1] = vb;
        ((uint2*)g_hhi)[i0] = ha; ((uint2*)g_hhi)[i1] = hb;
        if (threadIdx.x == 0) g_hn[row] = fminf(n, MAXN);
    } else {
        ((uint2*)g_xhi)[i0] = ha; ((uint2*)g_xhi)[i1] = hb;
        if (threadIdx.x == 0) g_xn[row] = fminf(n, MAXN);
    }
}

// split_w with 4 in-flight uint4 loads per thread (MLP boost)
struct SplitArgs { const float* src[5]; };
__global__ void __launch_bounds__(256) split_w_kernel(SplitArgs saw) {
    int w = blockIdx.y;
    size_t base = (size_t)blockIdx.x * 1024 + threadIdx.x;
    float4 v0 = ((const float4*)saw.src[w])[base];
    float4 v1 = ((const float4*)saw.src[w])[base + 256];
    float4 v2 = ((const float4*)saw.src[w])[base + 512];
    float4 v3 = ((const float4*)saw.src[w])[base + 768];
    size_t o = (size_t)w * (DD * DD / 4) + base;
    uint2 h0, h1, h2, h3;
    hi4h(v0, h0); hi4h(v1, h1); hi4h(v2, h2); hi4h(v3, h3);
    ((uint2*)g_whi)[o] = h0;
    ((uint2*)g_whi)[o + 256] = h1;
    ((uint2*)g_whi)[o + 512] = h2;
    ((uint2*)g_whi)[o + 768] = h3;
}

// fused: z gate -> g_z (fp32), r gate + r_point_h -> phi + rphn  (occ-3 forced)
__global__ void __launch_bounds__(256, 3) combine_zr_kernel(
    const __half* __restrict__ G0, const __half* __restrict__ G2, const float* __restrict__ bz,
    const __half* __restrict__ G1, const __half* __restrict__ G3, const float* __restrict__ br) {
    int row = blockIdx.x;
    const uint2* wz2 = (const uint2*)(G0 + (size_t)row * DD);
    const uint2* uz2 = (const uint2*)(G2 + (size_t)row * DD);
    const uint2* wr2 = (const uint2*)(G1 + (size_t)row * DD);
    const uint2* ur2 = (const uint2*)(G3 + (size_t)row * DD);
    const float4* bz4 = (const float4*)bz;
    const float4* br4 = (const float4*)br;
    const float4* hp4 = (const float4*)(g_hp + (size_t)row * DD);

    float4 wrv[2], urv[2], hv[2];
    float v[12];
#pragma unroll
    for (int q = 0; q < 12; q++) v[q] = 0.f;
#pragma unroll
    for (int it = 0; it < 2; it++) {
        int j = threadIdx.x + it * 256;
        float4 a = h4f(wz2[j]), b = h4f(uz2[j]), c = h4f(wr2[j]), d = h4f(ur2[j]);
        float4 e = bz4[j], f = br4[j];
        wrv[it] = c; urv[it] = d; hv[it] = hp4[j];
        v[0] += a.x * a.x + a.y * a.y + a.z * a.z + a.w * a.w;
        v[1] += b.x * b.x + b.y * b.y + b.z * b.z + b.w * b.w;
        v[2] += a.x * b.x + a.y * b.y + a.z * b.z + a.w * b.w;
        v[3] += a.x * e.x + a.y * e.y + a.z * e.z + a.w * e.w;
        v[4] += b.x * e.x + b.y * e.y + b.z * e.z + b.w * e.w;
        v[5] += e.x * e.x + e.y * e.y + e.z * e.z + e.w * e.w;
        v[6] += c.x * c.x + c.y * c.y + c.z * c.z + c.w * c.w;
        v[7] += d.x * d.x + d.y * d.y + d.z * d.z + d.w * d.w;
        v[8] += c.x * d.x + c.y * d.y + c.z * d.z + c.w * d.w;
        v[9] += c.x * f.x + c.y * f.y + c.z * f.z + c.w * f.w;
        v[10] += d.x * f.x + d.y * f.y + d.z * f.z + d.w * f.w;
        v[11] += f.x * f.x + f.y * f.y + f.z * f.z + f.w * f.w;
    }
    block_reduce<12>(v);

    float hn = g_hn[row], xn = g_xn[row];

    float fwz, fuz, fbz, f2z;
    transition_coefs(&v[0], hn, xn, fwz, fuz, fbz, f2z);
    float fnz = sqrtf(fmaxf(f2z, MINN));
    float lgz = artanh_c(fnz) / fnz;

    float fwr, fur, fbr, f2r;
    transition_coefs(&v[6], hn, xn, fwr, fur, fbr, f2r);
    float fnr = sqrtf(fmaxf(f2r, MINN));
    float lgr = artanh_c(fnr) / fnr;

    float tv[2][4];
    float s[1] = {0.f};
    float4* oz = (float4*)(g_z + (size_t)row * DD);
#pragma unroll
    for (int it = 0; it < 2; it++) {
        int j = threadIdx.x + it * 256;
        float4 a = h4f(wz2[j]), b = h4f(uz2[j]);
        float4 e = bz4[j];
        float t0 = lgz * (fwz * a.x + fuz * b.x + fbz * e.x);
        float t1 = lgz * (fwz * a.y + fuz * b.y + fbz * e.y);
        float t2 = lgz * (fwz * a.z + fuz * b.z + fbz * e.z);
        float t3 = lgz * (fwz * a.w + fuz * b.w + fbz * e.w);
        oz[j] = make_float4(1.f / (1.f + expf(-t0)), 1.f / (1.f + expf(-t1)),
                            1.f / (1.f + expf(-t2)), 1.f / (1.f + expf(-t3)));

        float4 c = wrv[it], d = urv[it], f = br4[j], h = hv[it];
        float r0 = 1.f / (1.f + expf(-lgr * (fwr * c.x + fur * d.x + fbr * f.x)));
        float r1 = 1.f / (1.f + expf(-lgr * (fwr * c.y + fur * d.y + fbr * f.y)));
        float r2 = 1.f / (1.f + expf(-lgr * (fwr * c.z + fur * d.z + fbr * f.z)));
        float r3 = 1.f / (1.f + expf(-lgr * (fwr * c.w + fur * d.w + fbr * f.w)));
        tv[it][0] = h.x * r0; tv[it][1] = h.y * r1; tv[it][2] = h.z * r2; tv[it][3] = h.w * r3;
        s[0] += tv[it][0] * tv[it][0] + tv[it][1] * tv[it][1] +
                tv[it][2] * tv[it][2] + tv[it][3] * tv[it][3];
    }
    block_reduce<1>(s);

    float ch = artanh_c(hn) / hn;
    float s2 = ch * ch * s[0];
    float nv = sqrtf(fmaxf(s2, MINN));
    float cpf = tanhf(nv) / nv * ch;
    float o2 = cpf * cpf * s[0];
    float on = sqrtf(fmaxf(o2, MINN));
    if (on > MAXN) { cpf *= MAXN / on; on = MAXN; }

#pragma unroll
    for (int it = 0; it < 2; it++) {
        int j = threadIdx.x + it * 256;
        float4 pv = make_float4(cpf * tv[it][0], cpf * tv[it][1], cpf * tv[it][2], cpf * tv[it][3]);
        uint2 hh;
        hi4h(pv, hh);
        size_t i4 = (size_t)row * (DD / 4) + j;
        ((uint2*)g_phi)[i4] = hh;
    }
    if (threadIdx.x == 0) g_rphn[row] = on;
}

// fused h_tilde transition + final mobius update -> out  (occ-3 forced)
__global__ void __launch_bounds__(256, 3) ht_final_kernel(
    const __half* __restrict__ Wh, const __half* __restrict__ Ux, const float* __restrict__ bias,
    float* __restrict__ out) {
    int row = blockIdx.x;
    const uint2* wr2 = (const uint2*)(Wh + (size_t)row * DD);
    const uint2* ur2 = (const uint2*)(Ux + (size_t)row * DD);
    const float4* bi4 = (const float4*)bias;
    const float4* hp4 = (const float4*)(g_hp + (size_t)row * DD);
    const float4* z4 = (const float4*)(g_z + (size_t)row * DD);
    float4 wv[2], uv4[2], hv[2], zv[2];
    float v[6] = {0.f, 0.f, 0.f, 0.f, 0.f, 0.f};
#pragma unroll
    for (int it = 0; it < 2; it++) {
        int j = threadIdx.x + it * 256;
        float4 w = h4f(wr2[j]), u = h4f(ur2[j]), b = bi4[j];
        wv[it] = w; uv4[it] = u; hv[it] = hp4[j]; zv[it] = z4[j];
        v[0] += w.x * w.x + w.y * w.y + w.z * w.z + w.w * w.w;
        v[1] += u.x * u.x + u.y * u.y + u.z * u.z + u.w * u.w;
        v[2] += w.x * u.x + w.y * u.y + w.z * u.z + w.w * u.w;
        v[3] += w.x * b.x + w.y * b.y + w.z * b.z + w.w * b.w;
        v[4] += u.x * b.x + u.y * b.y + u.z * b.z + u.w * b.w;
        v[5] += b.x * b.x + b.y * b.y + b.z * b.z + b.w * b.w;
    }
    block_reduce<6>(v);

    float fw, fu, fb, f2;
    transition_coefs(v, g_rphn[row], g_xn[row], fw, fu, fb, f2);

    float tvv[2][4];
#pragma unroll
    for (int it = 0; it < 2; it++) {
        int j = threadIdx.x + it * 256;
        float4 w = wv[it], u = uv4[it], b = bi4[j];  // bias reload (L2)
        tvv[it][0] = fw * w.x + fu * u.x + fb * b.x;
        tvv[it][1] = fw * w.y + fu * u.y + fb * b.y;
        tvv[it][2] = fw * w.z + fu * u.z + fb * b.z;
        tvv[it][3] = fw * w.w + fu * u.w + fb * b.w;
    }

    float hn = g_hn[row];
    float u2 = hn * hn;

    float r2v[2] = {0.f, 0.f};
#pragma unroll
    for (int it = 0; it < 2; it++) {
        float4 h = hv[it];
        r2v[0] += h.x * tvv[it][0] + h.y * tvv[it][1] + h.z * tvv[it][2] + h.w * tvv[it][3];
        r2v[1] += tvv[it][0] * tvv[it][0] + tvv[it][1] * tvv[it][1] +
                  tvv[it][2] * tvv[it][2] + tvv[it][3] * tvv[it][3];
    }
    block_reduce<2>(r2v);

    float uv = -r2v[0], v2 = r2v[1];
    float a = 1.f + 2.f * uv + v2;
    float c = 1.f - u2;
    float den = fmaxf(1.f + 2.f * uv + u2 * v2, MINN);
    float mh = -a / den, mt = c / den;
    float m2 = mh * mh * u2 + 2.f * mh * mt * r2v[0] + mt * mt * r2v[1];
    {
        float n = sqrtf(fmaxf(m2, MINN));
        if (n > MAXN) { float f = MAXN / n; mh *= f; mt *= f; m2 *= f * f; }
    }
    float mn = sqrtf(fmaxf(m2, MINN));
    float cm = artanh_c(mn) / mn;

    float w2[2] = {0.f, 0.f};
#pragma unroll
    for (int it = 0; it < 2; it++) {
        float4 h = hv[it], z = zv[it];
        float m0 = mh * h.x + mt * tvv[it][0], m1 = mh * h.y + mt * tvv[it][1];
        float m2e = mh * h.z + mt * tvv[it][2], m3 = mh * h.w + mt * tvv[it][3];
        float p0 = z.x * m0, p1 = z.y * m1, p2 = z.z * m2e, p3 = z.w * m3;
        w2[0] += p0 * p0 + p1 * p1 + p2 * p2 + p3 * p3;
        w2[1] += p0 * h.x + p1 * h.y + p2 * h.z + p3 * h.w;
    }
    block_reduce<2>(w2);

    float sv2 = cm * cm * w2[0];
    float nv = sqrtf(fmaxf(sv2, MINN));
    float cp = tanhf(nv) / nv * cm;
    float p2 = cp * cp * w2[0];
    {
        float n = sqrtf(fmaxf(p2, MINN));
        if (n > MAXN) { float f = MAXN / n; cp *= f; p2 *= f * f; }
    }

    float uv2 = cp * w2[1];
    float A = 1.f + 2.f * uv2 + p2;
    float C = 1.f - u2;
    float den3 = fmaxf(1.f + 2.f * uv2 + u2 * p2, MINN);
    float chh = A / den3;
    float cpp = C * cp / den3;
    float o2 = chh * chh * u2 + 2.f * chh * cpp * w2[1] + cpp * cpp * w2[0];
    {
        float n = sqrtf(fmaxf(o2, MINN));
        if (n > MAXN) { float f = MAXN / n; chh *= f; cpp *= f; }
    }

    float4* o = (float4*)(out + (size_t)row * DD);
#pragma unroll
    for (int it = 0; it < 2; it++) {
        int j = threadIdx.x + it * 256;
        float4 h = hv[it], z = zv[it];
        float m0 = mh * h.x + mt * tvv[it][0], m1 = mh * h.y + mt * tvv[it][1];
        float m2e = mh * h.z + mt * tvv[it][2], m3 = mh * h.w + mt * tvv[it][3];
        o[j] = make_float4(chh * h.x + cpp * z.x * m0, chh * h.y + cpp * z.y * m1,
                           chh * h.z + cpp * z.z * m2e, chh * h.w + cpp * z.w * m3);
    }
}

// =================== launch ===================
extern "C" void kernel_launch(void* const* d_in, const int* in_sizes, int n_in,
                              void* d_out, int out_size) {
    (void)in_sizes; (void)n_in; (void)out_size;
    const float* hyp_x = (const float*)d_in[0];
    const float* hidden = (const float*)d_in[1];
    const float* w_z = (const float*)d_in[2];
    const float* w_r = (const float*)d_in[3];
    const float* w_h = (const float*)d_in[4];
    const float* u_z = (const float*)d_in[5];
    const float* u_r = (const float*)d_in[6];
    const float* b_z = (const float*)d_in[7];
    const float* b_r = (const float*)d_in[8];
    const float* b_h = (const float*)d_in[9];
    float* out = (float*)d_out;

    __half *G0, *G1, *G2, *G3, *G4;
    __half *xhi, *hhi, *phi, *whi;
    cudaGetSymbolAddress((void**)&G0, g_G0);
    cudaGetSymbolAddress((void**)&G1, g_G1);
    cudaGetSymbolAddress((void**)&G2, g_G2);
    cudaGetSymbolAddress((void**)&G3, g_G3);
    cudaGetSymbolAddress((void**)&G4, g_G4);
    cudaGetSymbolAddress((void**)&xhi, g_xhi);
    cudaGetSymbolAddress((void**)&hhi, g_hhi);
    cudaGetSymbolAddress((void**)&phi, g_phi);
    cudaGetSymbolAddress((void**)&whi, g_whi);

    static int smem_set = 0;
    if (!smem_set) {
        cudaFuncSetAttribute(mma_gate_kernel, cudaFuncAttributeMaxDynamicSharedMemorySize,
                             G_SMEM);
        smem_set = 1;
    }

    const size_t WSZ = (size_t)DD * DD;

    // 1. project inputs + fp16 convert
    proj_norm_kernel<<<dim3(BB, 2), 256>>>(hyp_x, hidden);

    // 2. convert weights to fp16 (4 loads in flight per thread)
    SplitArgs saw;
    saw.src[0] = w_z; saw.src[1] = w_r; saw.src[2] = w_h; saw.src[3] = u_z; saw.src[4] = u_r;
    split_w_kernel<<<dim3(DD * DD / 4 / 1024, 5), 256>>>(saw);

    // 3. four independent fp16 GEMMs (fp16 outputs)
    GateArgs gg;
    gg.Ahi[0] = hhi; gg.Bhi[0] = whi + 0 * WSZ; gg.C[0] = G0;
    gg.Ahi[1] = hhi; gg.Bhi[1] = whi + 1 * WSZ; gg.C[1] = G1;
    gg.Ahi[2] = xhi; gg.Bhi[2] = whi + 3 * WSZ; gg.C[2] = G2;
    gg.Ahi[3] = xhi; gg.Bhi[3] = whi + 4 * WSZ; gg.C[3] = G3;
    mma_gate_kernel<<<dim3(16, 16, 4), 256, G_SMEM>>>(gg);

    // 4. fused z gate + r gate + r_point_h (z fp32, phi fp16)
    combine_zr_kernel<<<BB, 256>>>(G0, G2, b_z, G1, G3, b_r);

    // 5. G4 = rph @ w_h (fp16)
    GateArgs g4;
    g4.Ahi[0] = phi; g4.Bhi[0] = whi + 2 * WSZ; g4.C[0] = G4;
    g4.Ahi[1] = phi; g4.Bhi[1] = whi + 2 * WSZ; g4.C[1] = G4;
    g4.Ahi[2] = phi; g4.Bhi[2] = whi + 2 * WSZ; g4.C[2] = G4;
    g4.Ahi[3] = phi; g4.Bhi[3] = whi + 2 * WSZ; g4.C[3] = G4;
    mma_gate_kernel<<<dim3(16, 16, 1), 256, G_SMEM>>>(g4);

    // 6. fused h_tilde + final (reuses G3 = xp@u_r per reference)
    ht_final_kernel<<<BB, 256>>>(G4, G3, b_h, out);
}